// round 12
// baseline (speedup 1.0000x reference)
#include <cuda_runtime.h>
#include <cstdint>

#define B_  4
#define S_  2048
#define D_  1024
#define H_  16
#define DH_ 64
#define M_  (B_*S_)   // 8192 tokens
#define BH_ (B_*H_)   // 64

// Scratch (device globals: allocation-free per harness rules)
__device__ unsigned short g_qh[(size_t)BH_*S_*DH_];     // fp16 [bh][s][d]  (pre-scaled by 1/4096)
__device__ unsigned short g_kh[(size_t)BH_*S_*DH_];     // fp16 [bh][s][d]
__device__ unsigned       g_vp[(size_t)BH_*(S_/2)*DH_]; // half2 (v[2k],v[2k+1]) [bh][k2][d]
__device__ unsigned short g_ctxh[(size_t)M_*D_];        // fp16 [m][d]
__device__ unsigned short g_ah[3][(size_t)M_*D_];       // fp16 copies of query/key/value
__device__ unsigned       g_wp[4][(size_t)(D_/2)*D_];   // half2 pair-packed weights [k2][n]

// ---------------------------------------------------------------------------
__device__ __forceinline__ unsigned f2h2(float lo, float hi) {
    unsigned r; asm("cvt.rn.f16x2.f32 %0, %1, %2;" : "=r"(r) : "f"(hi), "f"(lo));
    return r;
}
__device__ __forceinline__ void mma16(float* c, const unsigned* a, const unsigned* b) {
    asm volatile("mma.sync.aligned.m16n8k16.row.col.f32.f16.f16.f32 "
        "{%0,%1,%2,%3}, {%4,%5,%6,%7}, {%8,%9}, {%0,%1,%2,%3};"
        : "+f"(c[0]), "+f"(c[1]), "+f"(c[2]), "+f"(c[3])
        : "r"(a[0]), "r"(a[1]), "r"(a[2]), "r"(a[3]), "r"(b[0]), "r"(b[1]));
}
__device__ __forceinline__ void cpa16(uint32_t dst, const void* src) {
    asm volatile("cp.async.cg.shared.global [%0], [%1], 16;" :: "r"(dst), "l"(src));
}
__device__ __forceinline__ void ldsm4(unsigned* r, uint32_t addr) {
    asm volatile("ldmatrix.sync.aligned.m8n8.x4.shared.b16 {%0,%1,%2,%3}, [%4];"
        : "=r"(r[0]), "=r"(r[1]), "=r"(r[2]), "=r"(r[3]) : "r"(addr));
}
#define CP_COMMIT() asm volatile("cp.async.commit_group;" ::: "memory")
#define CP_WAIT2()  asm volatile("cp.async.wait_group 2;" ::: "memory")
#define CP_WAIT1()  asm volatile("cp.async.wait_group 1;" ::: "memory")

// ---------------------------------------------------------------------------
// Pre-pass (fused): fp32 -> fp16 copies; weight pair-packing
// ---------------------------------------------------------------------------
__global__ __launch_bounds__(256) void cvt_h3(
    const float4* __restrict__ i0, const float4* __restrict__ i1,
    const float4* __restrict__ i2,
    uint2* __restrict__ o0, uint2* __restrict__ o1, uint2* __restrict__ o2)
{
    const float4* in = (blockIdx.y == 0) ? i0 : (blockIdx.y == 1) ? i1 : i2;
    uint2* out       = (blockIdx.y == 0) ? o0 : (blockIdx.y == 1) ? o1 : o2;
    const int i = blockIdx.x * 256 + threadIdx.x;
    float4 v = in[i];
    out[i] = make_uint2(f2h2(v.x, v.y), f2h2(v.z, v.w));
}
__global__ __launch_bounds__(256) void pack_w4(
    const float* __restrict__ w0, const float* __restrict__ w1,
    const float* __restrict__ w2, const float* __restrict__ w3,
    unsigned* __restrict__ p0, unsigned* __restrict__ p1,
    unsigned* __restrict__ p2, unsigned* __restrict__ p3)
{
    const int y = blockIdx.y;
    const float* W = (y == 0) ? w0 : (y == 1) ? w1 : (y == 2) ? w2 : w3;
    unsigned* Wp   = (y == 0) ? p0 : (y == 1) ? p1 : (y == 2) ? p2 : p3;
    const int i = blockIdx.x * 256 + threadIdx.x;   // over 512*256
    const int k2 = i >> 8, c4 = i & 255;
    float4 r0 = *(const float4*)(W + (size_t)(2*k2    ) * D_ + c4 * 4);
    float4 r1 = *(const float4*)(W + (size_t)(2*k2 + 1) * D_ + c4 * 4);
    *(uint4*)(Wp + (size_t)k2 * D_ + c4 * 4) =
        make_uint4(f2h2(r0.x, r1.x), f2h2(r0.y, r1.y),
                   f2h2(r0.z, r1.z), f2h2(r0.w, r1.w));
}

// ---------------------------------------------------------------------------
// GEMM: out = A[M,1024](fp16) @ W(pair-packed) + bias, fp16 mma, fp32 accum.
// Block 128x128, K-tile 32, 4-stage cp.async pipeline, ldmatrix A frags.
// gridDim.z==3: z0 -> fp16 split-head *scaled 1/4096* (q); z1 -> fp16
// split-head (k); z2 -> pair-packed V. gridDim.z==1: fp32 row-major out.
// ---------------------------------------------------------------------------
#define ASTR 20                    // 16 data words + pad 4 (80B rows, 16B-aligned)
#define BSTR 136                   // 128 data words + pad 8
#define ABUF (128*ASTR)            // 2560 words
#define BBUF (16*BSTR)             // 2176 words
#define STGW (ABUF+BBUF)           // 4736 words per stage
#define GSMEM (4*STGW*4)           // 75776 bytes

__global__ __launch_bounds__(256, 2) void gemm_h(
    const unsigned short* __restrict__ A0, const unsigned short* __restrict__ A1,
    const unsigned short* __restrict__ A2,
    const unsigned* __restrict__ W0, const unsigned* __restrict__ W1,
    const unsigned* __restrict__ W2,
    const float* __restrict__ bb0, const float* __restrict__ bb1,
    const float* __restrict__ bb2,
    void* o0, void* o1, void* o2)
{
    extern __shared__ unsigned gsm[];
    const int z = blockIdx.z;
    const unsigned short* A = (z == 0) ? A0 : (z == 1) ? A1 : A2;
    const unsigned* Wp      = (z == 0) ? W0 : (z == 1) ? W1 : W2;
    const float* bias       = (z == 0) ? bb0 : (z == 1) ? bb1 : bb2;
    void* outp              = (z == 0) ? o0 : (z == 1) ? o1 : o2;
    const int om = (gridDim.z == 3) ? ((z == 2) ? 2 : 1) : 0;
    const float osc = (gridDim.z == 3 && z == 0) ? (1.0f / 4096.0f) : 1.0f;

    const int tid  = threadIdx.x;
    const int lane = tid & 31, warp = tid >> 5;
    const int wm = (warp >> 2) * 64, wn = (warp & 3) * 32;
    const int g = lane >> 2, t = lane & 3;
    const int bm = blockIdx.y * 128, bn = blockIdx.x * 128;

    const uint32_t sb0 = (uint32_t)__cvta_generic_to_shared(gsm);

    // ldmatrix lane addresses for A (per mt tile), byte offsets within a stage
    int amt_off[4];
#pragma unroll
    for (int mt = 0; mt < 4; mt++)
        amt_off[mt] = ((wm + mt*16 + (lane & 15)) * ASTR + (lane >> 4) * 4) * 4;

    float acc[4][4][4];
#pragma unroll
    for (int mt = 0; mt < 4; mt++)
#pragma unroll
        for (int nt = 0; nt < 4; nt++)
#pragma unroll
            for (int i = 0; i < 4; i++) acc[mt][nt][i] = 0.f;

#define ISSUE(s) do {                                                           \
        const uint32_t sb = sb0 + ((s) & 3) * (STGW * 4);                       \
        const int k0 = (s) * 32;                                                \
        _Pragma("unroll")                                                       \
        for (int i = 0; i < 2; i++) {                                           \
            const int idx = tid + i * 256;                                      \
            const int row = idx >> 2, c16 = idx & 3;                            \
            cpa16(sb + (row * ASTR + c16 * 4) * 4,                              \
                  A + (size_t)(bm + row) * D_ + k0 + c16 * 8);                  \
            const int kr = idx >> 5, c = idx & 31;                              \
            cpa16(sb + (ABUF + kr * BSTR + c * 4) * 4,                          \
                  Wp + (size_t)(k0 / 2 + kr) * D_ + bn + c * 4);                \
        }                                                                       \
    } while (0)

    ISSUE(0); CP_COMMIT();
    ISSUE(1); CP_COMMIT();
    ISSUE(2); CP_COMMIT();

    for (int kc = 0; kc < 32; kc++) {
        CP_WAIT2();
        __syncthreads();
        const uint32_t sbs = sb0 + (kc & 3) * (STGW * 4);
        const unsigned* Bp = gsm + (kc & 3) * STGW + ABUF;
#pragma unroll
        for (int ks = 0; ks < 2; ks++) {
            unsigned af[4][4], bf[4][2];
#pragma unroll
            for (int mt = 0; mt < 4; mt++)
                ldsm4(af[mt], sbs + amt_off[mt] + ks * 32);
#pragma unroll
            for (int nt = 0; nt < 4; nt++) {
                bf[nt][0] = Bp[(ks*8 + t    ) * BSTR + wn + nt*8 + g];
                bf[nt][1] = Bp[(ks*8 + t + 4) * BSTR + wn + nt*8 + g];
            }
#pragma unroll
            for (int mt = 0; mt < 4; mt++)
#pragma unroll
                for (int nt = 0; nt < 4; nt++)
                    mma16(acc[mt][nt], af[mt], bf[nt]);
        }
        if (kc < 29) ISSUE(kc + 3);
        CP_COMMIT();
    }
#undef ISSUE

    // epilogue
#pragma unroll
    for (int mt = 0; mt < 4; mt++) {
#pragma unroll
        for (int nt = 0; nt < 4; nt++) {
            const int row0 = bm + wm + mt * 16 + g;
            const int col  = bn + wn + nt * 8 + t * 2;
            const float c0 = bias[col], c1 = bias[col + 1];
            const float y0 = (acc[mt][nt][0] + c0) * osc, y1 = (acc[mt][nt][1] + c1) * osc;
            const float y2 = (acc[mt][nt][2] + c0) * osc, y3 = (acc[mt][nt][3] + c1) * osc;
            if (om == 0) {
                float* out = (float*)outp;
                *(float2*)(out + (size_t)row0 * D_ + col)       = make_float2(y0, y1);
                *(float2*)(out + (size_t)(row0 + 8) * D_ + col) = make_float2(y2, y3);
            } else if (om == 1) {
                unsigned* out = (unsigned*)outp;   // half2 words [bh][s][32]
                const int h = col >> 6, dw = (col & 63) >> 1;
                const int b0i = row0 >> 11, s0 = row0 & 2047;
                out[(((size_t)(b0i * H_ + h)) * S_ + s0    ) * 32 + dw] = f2h2(y0, y1);
                out[(((size_t)(b0i * H_ + h)) * S_ + s0 + 8) * 32 + dw] = f2h2(y2, y3);
            } else {
                const float p0 = __shfl_xor_sync(0xffffffffu, y0, 4);
                const float p1 = __shfl_xor_sync(0xffffffffu, y1, 4);
                const float p2 = __shfl_xor_sync(0xffffffffu, y2, 4);
                const float p3 = __shfl_xor_sync(0xffffffffu, y3, 4);
                if (!(g & 1)) {
                    unsigned* out = (unsigned*)outp;   // [bh][k2][64] words
                    const int h = col >> 6, d = col & 63;
                    const int b0i = row0 >> 11, s0 = row0 & 2047;
                    const size_t base = ((size_t)(b0i * H_ + h)) * (S_/2) * DH_;
                    uint2 wlo = make_uint2(f2h2(y0, p0), f2h2(y1, p1));
                    uint2 whi = make_uint2(f2h2(y2, p2), f2h2(y3, p3));
                    *(uint2*)&out[base + (size_t)(s0 >> 1) * DH_ + d]       = wlo;
                    *(uint2*)&out[base + (size_t)((s0 + 8) >> 1) * DH_ + d] = whi;
                }
            }
        }
    }
}

// ---------------------------------------------------------------------------
// Flash attention, fp16 mma, cp.async 2-stage K/V pipeline.
// Q pre-scaled by 1/4096 (exact power of 2) -> softmax is exp(s) directly.
// Interior tiles skip causal predicates; fully-future tiles skip all compute.
// ---------------------------------------------------------------------------
#define QSTR 40
#define KSTR 40
#define VSTR 72
#define AVOFF 2560                 // words: after K (64*40)
#define AMOFF (2560 + 32*72)       // 4864: after V (32*72)
#define ASTG  (AMOFF + 64)         // 4928 words per stage
#define ATT_SMEM (2 * ASTG * 4)    // 39424 B (Q staging = 5120 w fits)

__global__ __launch_bounds__(256, 2) void attn_h(
    const unsigned short* __restrict__ gq, const unsigned short* __restrict__ gk,
    const unsigned* __restrict__ gvp, const int* __restrict__ mask,
    unsigned* __restrict__ ctx)
{
    extern __shared__ unsigned smA[];
    const uint32_t sb0 = (uint32_t)__cvta_generic_to_shared(smA);

    const int tid  = threadIdx.x;
    const int lane = tid & 31, warp = tid >> 5;
    const int g = lane >> 2, t = lane & 3;
    const int bh = blockIdx.y, b = bh >> 4, h = bh & 15;
    const int it = blockIdx.x, qbase = it * 128;

    // stage Q (row-major fp16, QSTR words per row) in stage memory
    const unsigned short* qp = gq + ((size_t)bh * S_ + qbase) * DH_;
#pragma unroll
    for (int i = 0; i < 4; i++) {
        const int idx = tid + i * 256;
        const int row = idx >> 3, c8 = idx & 7;
        uint4 v = *(const uint4*)(qp + (size_t)row * DH_ + c8 * 8);
        *(uint4*)&smA[row * QSTR + c8 * 4] = v;
    }
    __syncthreads();

    const int r0 = warp * 16 + g;
    unsigned qf[4][4];
#pragma unroll
    for (int ks = 0; ks < 4; ks++) {
        qf[ks][0] = smA[(r0    ) * QSTR + ks*8 + t];
        qf[ks][1] = smA[(r0 + 8) * QSTR + ks*8 + t];
        qf[ks][2] = smA[(r0    ) * QSTR + ks*8 + t + 4];
        qf[ks][3] = smA[(r0 + 8) * QSTR + ks*8 + t + 4];
    }
    __syncthreads();   // Q staging consumed; stages may be overwritten

    float l0 = 0.f, l1 = 0.f;
    float o[8][4];
#pragma unroll
    for (int nt = 0; nt < 8; nt++)
#pragma unroll
        for (int i = 0; i < 4; i++) o[nt][i] = 0.f;

    const int row0g = qbase + r0;
    const int row1g = row0g + 8;
    const int wrow_min = qbase + warp * 16;        // min q-row in warp tile
    const int wrow_max = qbase + warp * 16 + 15;   // max q-row in warp tile
    const int jtmax = 2 * it + 1;

#define AISSUE(j) do {                                                          \
        const uint32_t stb = sb0 + ((j) & 1) * (ASTG * 4);                      \
        const unsigned short* kp_ = gk + ((size_t)bh * S_ + (j) * 64) * DH_;    \
        const unsigned* vp_ = gvp + ((size_t)bh * (S_/2) + (j) * 32) * DH_;     \
        _Pragma("unroll")                                                       \
        for (int i = 0; i < 2; i++) {                                           \
            const int idx = tid + i * 256;                                      \
            const int krow = idx >> 3, c8 = idx & 7;                            \
            cpa16(stb + (krow * KSTR + c8 * 4) * 4,                             \
                  kp_ + (size_t)krow * DH_ + c8 * 8);                           \
            const int k2 = idx >> 4, c4 = idx & 15;                             \
            cpa16(stb + (AVOFF + k2 * VSTR + c4 * 4) * 4,                       \
                  vp_ + (size_t)k2 * DH_ + c4 * 4);                             \
        }                                                                       \
        if (tid < 16)                                                           \
            cpa16(stb + (AMOFF + tid * 4) * 4,                                  \
                  mask + (size_t)b * S_ + (j) * 64 + tid * 4);                  \
    } while (0)

    AISSUE(0); CP_COMMIT();

    for (int jt = 0; jt <= jtmax; jt++) {
        if (jt < jtmax) AISSUE(jt + 1);
        CP_COMMIT();
        CP_WAIT1();
        __syncthreads();   // stage jt visible to all warps

        const unsigned* Ksl = smA + (jt & 1) * ASTG;
        const unsigned* Vpl = Ksl + AVOFF;
        const int* mskl = (const int*)(Ksl + AMOFF);
        const int kb = jt * 64;

        if (kb <= wrow_max) {   // else: all keys in this tile are future -> skip
            // ---- S = Q @ K^T (Q pre-scaled) ----
            float s[8][4];
#pragma unroll
            for (int nt = 0; nt < 8; nt++)
#pragma unroll
                for (int i = 0; i < 4; i++) s[nt][i] = 0.f;
#pragma unroll
            for (int ks = 0; ks < 4; ks++) {
#pragma unroll
                for (int nt = 0; nt < 8; nt++) {
                    unsigned bfr[2];
                    bfr[0] = Ksl[(nt*8 + g) * KSTR + ks*8 + t];
                    bfr[1] = Ksl[(nt*8 + g) * KSTR + ks*8 + t + 4];
                    mma16(s[nt], qf[ks], bfr);
                }
            }

            // ---- softmax (fixed m=0) + pack P ----
            unsigned pk0[8], pk1[8];
            float sum0 = 0.f, sum1 = 0.f;
            if (kb + 63 <= wrow_min) {
                // interior: no causal predicates
#pragma unroll
                for (int nt = 0; nt < 8; nt++) {
                    const int colb = nt*8 + t*2;
                    const bool mk0 = mskl[colb] != 0, mk1 = mskl[colb+1] != 0;
                    const float e0 = mk0 ? __expf(s[nt][0]) : 0.f;
                    const float e1 = mk1 ? __expf(s[nt][1]) : 0.f;
                    const float e2 = mk0 ? __expf(s[nt][2]) : 0.f;
                    const float e3 = mk1 ? __expf(s[nt][3]) : 0.f;
                    sum0 += e0 + e1;  sum1 += e2 + e3;
                    pk0[nt] = f2h2(e0, e1);
                    pk1[nt] = f2h2(e2, e3);
                }
            } else {
                // diagonal: full causal + mask predicates
#pragma unroll
                for (int nt = 0; nt < 8; nt++) {
                    const int colb = nt*8 + t*2;
                    const int key  = kb + colb;
                    const bool mk0 = mskl[colb] != 0, mk1 = mskl[colb+1] != 0;
                    const float e0 = (mk0 && key     <= row0g) ? __expf(s[nt][0]) : 0.f;
                    const float e1 = (mk1 && key + 1 <= row0g) ? __expf(s[nt][1]) : 0.f;
                    const float e2 = (mk0 && key     <= row1g) ? __expf(s[nt][2]) : 0.f;
                    const float e3 = (mk1 && key + 1 <= row1g) ? __expf(s[nt][3]) : 0.f;
                    sum0 += e0 + e1;  sum1 += e2 + e3;
                    pk0[nt] = f2h2(e0, e1);
                    pk1[nt] = f2h2(e2, e3);
                }
            }
            sum0 += __shfl_xor_sync(0xffffffffu, sum0, 1);
            sum0 += __shfl_xor_sync(0xffffffffu, sum0, 2);
            sum1 += __shfl_xor_sync(0xffffffffu, sum1, 1);
            sum1 += __shfl_xor_sync(0xffffffffu, sum1, 2);
            l0 += sum0;  l1 += sum1;

            // ---- O += P @ V (A frags from registers) ----
#pragma unroll
            for (int ks2 = 0; ks2 < 4; ks2++) {
                unsigned a[4] = { pk0[2*ks2], pk1[2*ks2], pk0[2*ks2+1], pk1[2*ks2+1] };
#pragma unroll
                for (int nt = 0; nt < 8; nt++) {
                    unsigned bfr[2];
                    bfr[0] = Vpl[(ks2*8 + t    ) * VSTR + nt*8 + g];
                    bfr[1] = Vpl[(ks2*8 + t + 4) * VSTR + nt*8 + g];
                    mma16(o[nt], a, bfr);
                }
            }
        }
        __syncthreads();   // all warps done with stage jt before it is re-issued
    }
#undef AISSUE

    const float il0 = 1.0f / fmaxf(l0, 1e-30f);
    const float il1 = 1.0f / fmaxf(l1, 1e-30f);
    unsigned* op0 = ctx + ((size_t)(b * S_) + row0g) * (D_/2) + h * 32;
    unsigned* op1 = op0 + (size_t)8 * (D_/2);
#pragma unroll
    for (int nt = 0; nt < 8; nt++) {
        op0[nt*4 + t] = f2h2(o[nt][0] * il0, o[nt][1] * il0);
        op1[nt*4 + t] = f2h2(o[nt][2] * il1, o[nt][3] * il1);
    }
}

// ---------------------------------------------------------------------------
extern "C" void kernel_launch(void* const* d_in, const int* in_sizes, int n_in,
                              void* d_out, int out_size)
{
    const float* query = (const float*)d_in[0];
    const float* key   = (const float*)d_in[1];
    const float* value = (const float*)d_in[2];
    const int*   mask  = (const int*)  d_in[3];
    const float* Wq = (const float*)d_in[4];  const float* bq = (const float*)d_in[5];
    const float* Wk = (const float*)d_in[6];  const float* bk = (const float*)d_in[7];
    const float* Wv = (const float*)d_in[8];  const float* bv = (const float*)d_in[9];
    const float* Wo = (const float*)d_in[10]; const float* bo = (const float*)d_in[11];

    unsigned short *qh, *kh, *ctxh, *ah; unsigned *vp, *wp;
    cudaGetSymbolAddress((void**)&qh,   g_qh);
    cudaGetSymbolAddress((void**)&kh,   g_kh);
    cudaGetSymbolAddress((void**)&vp,   g_vp);
    cudaGetSymbolAddress((void**)&ctxh, g_ctxh);
    cudaGetSymbolAddress((void**)&ah,   g_ah);
    cudaGetSymbolAddress((void**)&wp,   g_wp);
    unsigned short* aq = ah;
    unsigned short* ak = ah + (size_t)M_*D_;
    unsigned short* av = ah + 2*(size_t)M_*D_;
    unsigned* wpq = wp;
    unsigned* wpk = wp + (size_t)(D_/2)*D_;
    unsigned* wpv = wp + 2*(size_t)(D_/2)*D_;
    unsigned* wpo = wp + 3*(size_t)(D_/2)*D_;

    const int n4 = M_ * D_ / 4;
    cvt_h3<<<dim3(n4 / 256, 3), 256>>>(
        (const float4*)query, (const float4*)key, (const float4*)value,
        (uint2*)aq, (uint2*)ak, (uint2*)av);
    pack_w4<<<dim3(512, 4), 256>>>(Wq, Wk, Wv, Wo, wpq, wpk, wpv, wpo);

    cudaFuncSetAttribute(gemm_h, cudaFuncAttributeMaxDynamicSharedMemorySize, GSMEM);
    gemm_h<<<dim3(8, 64, 3), 256, GSMEM>>>(
        aq, ak, av, wpq, wpk, wpv, bq, bk, bv, (void*)qh, (void*)kh, (void*)vp);

    cudaFuncSetAttribute(attn_h, cudaFuncAttributeMaxDynamicSharedMemorySize, ATT_SMEM);
    attn_h<<<dim3(S_ / 128, BH_), 256, ATT_SMEM>>>(qh, kh, vp, mask, (unsigned*)ctxh);

    gemm_h<<<dim3(8, 64, 1), 256, GSMEM>>>(
        ctxh, ctxh, ctxh, wpo, wpo, wpo, bo, bo, bo, d_out, d_out, d_out);
}